// round 15
// baseline (speedup 1.0000x reference)
#include <cuda_runtime.h>
#include <cuda_bf16.h>
#include <cstdint>
#include <math.h>

// Problem dims
#define BB 2
#define SS 2048
#define DD 1024
#define HH 16
#define DK 64
#define MROWS (BB * SS)   // 4096
#define BHT (BB * HH)     // 32

// -------- scratch (static __device__ globals; no allocation allowed) --------
__device__ __nv_bfloat16 g_Ph[(size_t)BB * HH * SS * SS];         // 256 MB E hi (exp scores)
__device__ __nv_bfloat16 g_Pl[(size_t)BB * HH * SS * SS];         // 256 MB E lo
__device__ float g_RS[(size_t)BHT * SS * 32];                     // 8 MB per-row per-kt64 partial sums

// bf16 hi/lo planes
__device__ __nv_bfloat16 g_Xh[(size_t)MROWS * DD], g_Xl[(size_t)MROWS * DD];
__device__ __nv_bfloat16 g_Zh[(size_t)MROWS * DD], g_Zl[(size_t)MROWS * DD];
__device__ __nv_bfloat16 g_Qh[(size_t)MROWS * DD], g_Ql[(size_t)MROWS * DD];
__device__ __nv_bfloat16 g_Kh[(size_t)MROWS * DD], g_Kl[(size_t)MROWS * DD];
__device__ __nv_bfloat16 g_Ch[(size_t)MROWS * DD], g_Cl[(size_t)MROWS * DD];
__device__ __nv_bfloat16 g_Wqh[(size_t)DD * DD], g_Wql[(size_t)DD * DD];
__device__ __nv_bfloat16 g_Wkh[(size_t)DD * DD], g_Wkl[(size_t)DD * DD];
__device__ __nv_bfloat16 g_Woh[(size_t)DD * DD], g_Wol[(size_t)DD * DD];

// ============================================================================
// helpers
// ============================================================================
__device__ __forceinline__ uint32_t smem_u32(const void* p) {
    uint32_t a;
    asm("{ .reg .u64 t; cvta.to.shared.u64 t, %1; cvt.u32.u64 %0, t; }" : "=r"(a) : "l"(p));
    return a;
}

__device__ __forceinline__ uint32_t pack_bf16(__nv_bfloat16 a, __nv_bfloat16 b) {
    return (uint32_t)__bfloat16_as_ushort(a) | ((uint32_t)__bfloat16_as_ushort(b) << 16);
}

// cheap split: hi = truncated top-16 bits (free), lo = rn(v - hi)
__device__ __forceinline__ void split1(float v, __nv_bfloat16& h, __nv_bfloat16& l) {
    const uint32_t u = __float_as_uint(v);
    h = __ushort_as_bfloat16((unsigned short)(u >> 16));
    const float hf = __uint_as_float(u & 0xFFFF0000u);
    l = __float2bfloat16_rn(v - hf);
}

#define MMA_BF16(C, A0, A1, A2, A3, B0, B1) \
    asm volatile( \
        "mma.sync.aligned.m16n8k16.row.col.f32.bf16.bf16.f32 " \
        "{%0,%1,%2,%3}, {%4,%5,%6,%7}, {%8,%9}, {%0,%1,%2,%3};" \
        : "+f"((C)[0]), "+f"((C)[1]), "+f"((C)[2]), "+f"((C)[3]) \
        : "r"(A0), "r"(A1), "r"(A2), "r"(A3), "r"(B0), "r"(B1))

__device__ __forceinline__ void ldsm4(uint32_t* r, uint32_t addr) {
    asm volatile("ldmatrix.sync.aligned.m8n8.x4.shared.b16 {%0,%1,%2,%3}, [%4];"
        : "=r"(r[0]), "=r"(r[1]), "=r"(r[2]), "=r"(r[3]) : "r"(addr));
}
__device__ __forceinline__ void ldsm4t(uint32_t* r, uint32_t addr) {
    asm volatile("ldmatrix.sync.aligned.m8n8.x4.trans.shared.b16 {%0,%1,%2,%3}, [%4];"
        : "=r"(r[0]), "=r"(r[1]), "=r"(r[2]), "=r"(r[3]) : "r"(addr));
}

// shared-memory pitch (bf16 elements): 72 -> 144B rows -> conflict-free LDSM
#define GP 72
#define PLANE (128 * GP * 2)          // 18432 bytes per 128-row plane
#define TOFF  (16 * GP * 2)           // byte offset of 16 rows = 2304

// ============================================================================
// fused fp32 -> bf16 hi/lo split over {x, z, wq, wk, wo}
// ============================================================================
#define NX ((size_t)MROWS * DD)       // 4194304
#define NW ((size_t)DD * DD)          // 1048576

__global__ __launch_bounds__(256) void cvt_split_all(
    const float* __restrict__ x, const float* __restrict__ z,
    const float* __restrict__ wq, const float* __restrict__ wk,
    const float* __restrict__ wo)
{
    const size_t i4 = ((size_t)blockIdx.x * 256 + threadIdx.x) * 4;
    const float* src;
    __nv_bfloat16 *hi, *lo;
    if (i4 < NX)               { src = x  + i4;                 hi = g_Xh + i4;                 lo = g_Xl + i4; }
    else if (i4 < 2 * NX)      { size_t j = i4 - NX;            src = z  + j; hi = g_Zh + j;    lo = g_Zl + j; }
    else if (i4 < 2 * NX + NW) { size_t j = i4 - 2 * NX;        src = wq + j; hi = g_Wqh + j;   lo = g_Wql + j; }
    else if (i4 < 2 * NX + 2 * NW) { size_t j = i4 - 2 * NX - NW; src = wk + j; hi = g_Wkh + j; lo = g_Wkl + j; }
    else                       { size_t j = i4 - 2 * NX - 2 * NW; src = wo + j; hi = g_Woh + j; lo = g_Wol + j; }

    const float4 v = *(const float4*)src;
    __nv_bfloat16 h0, h1, h2, h3, l0, l1, l2, l3;
    split1(v.x, h0, l0); split1(v.y, h1, l1);
    split1(v.z, h2, l2); split1(v.w, h3, l3);
    uint2 ph, pl;
    ph.x = pack_bf16(h0, h1); ph.y = pack_bf16(h2, h3);
    pl.x = pack_bf16(l0, l1); pl.y = pack_bf16(l2, l3);
    *(uint2*)hi = ph;
    *(uint2*)lo = pl;
}

// ============================================================================
// bf16x3 GEMM (ldmatrix frags, reg-pipelined loads): Y = A @ W^T + bias
// 512 thr / 16 warps, CTA 128x128, warp 32x32, K-chunk 64
// ============================================================================
#define GEMM_SMEM (4 * PLANE)         // 73728

template<bool OUTF32>
__global__ void __launch_bounds__(512, 1) gemm_pre(
    const __nv_bfloat16* __restrict__ Ah_g, const __nv_bfloat16* __restrict__ Al_g,
    const __nv_bfloat16* __restrict__ Wh_g, const __nv_bfloat16* __restrict__ Wl_g,
    const float* __restrict__ bias,
    float* __restrict__ Y,
    __nv_bfloat16* __restrict__ Yh, __nv_bfloat16* __restrict__ Yl,
    int K, int N)
{
    extern __shared__ char sm[];
    const uint32_t sb = smem_u32(sm);
    __nv_bfloat16* smAh = (__nv_bfloat16*)(sm);
    __nv_bfloat16* smAl = (__nv_bfloat16*)(sm + PLANE);
    __nv_bfloat16* smWh = (__nv_bfloat16*)(sm + 2 * PLANE);
    __nv_bfloat16* smWl = (__nv_bfloat16*)(sm + 3 * PLANE);

    const int tid = threadIdx.x;
    const int lane = tid & 31;
    const int wid = tid >> 5;
    const int wy = wid >> 2;
    const int wx = wid & 3;
    const int m0 = blockIdx.y * 128;
    const int n0 = blockIdx.x * 128;

    const int srow = tid >> 2;
    const int sk0 = (tid & 3) << 4;
    const __nv_bfloat16* pAh = Ah_g + (size_t)(m0 + srow) * K + sk0;
    const __nv_bfloat16* pAl = Al_g + (size_t)(m0 + srow) * K + sk0;
    const __nv_bfloat16* pWh = Wh_g + (size_t)(n0 + srow) * K + sk0;
    const __nv_bfloat16* pWl = Wl_g + (size_t)(n0 + srow) * K + sk0;
    const int sidx = srow * GP + sk0;

    const int lr = lane & 7;
    const int lm01 = (lane >> 3) & 1;
    const int lm23 = lane >> 4;
    const uint32_t aA = sb + (uint32_t)((((wy * 32 + lm01 * 8 + lr) * GP) + lm23 * 8) << 1);
    const uint32_t aW = sb + 2 * PLANE +
        (uint32_t)((((wx * 32 + lm23 * 8 + lr) * GP) + lm01 * 8) << 1);

    float acc[2][4][4];
#pragma unroll
    for (int t = 0; t < 2; t++)
#pragma unroll
        for (int u = 0; u < 4; u++)
#pragma unroll
            for (int i = 0; i < 4; i++) acc[t][u][i] = 0.f;

    const int r8 = lane >> 2;
    const int q2 = (lane & 3) << 1;
    const int nchunk = K >> 6;

    uint4 rg[8];
    auto loadregs = [&](int c) {
        const int kc = c << 6;
        rg[0] = *(const uint4*)(pAh + kc); rg[1] = *(const uint4*)(pAh + kc + 8);
        rg[2] = *(const uint4*)(pAl + kc); rg[3] = *(const uint4*)(pAl + kc + 8);
        rg[4] = *(const uint4*)(pWh + kc); rg[5] = *(const uint4*)(pWh + kc + 8);
        rg[6] = *(const uint4*)(pWl + kc); rg[7] = *(const uint4*)(pWl + kc + 8);
    };

    loadregs(0);
    for (int c = 0; c < nchunk; c++) {
        if (c > 0) __syncthreads();
        *(uint4*)(smAh + sidx)     = rg[0]; *(uint4*)(smAh + sidx + 8) = rg[1];
        *(uint4*)(smAl + sidx)     = rg[2]; *(uint4*)(smAl + sidx + 8) = rg[3];
        *(uint4*)(smWh + sidx)     = rg[4]; *(uint4*)(smWh + sidx + 8) = rg[5];
        *(uint4*)(smWl + sidx)     = rg[6]; *(uint4*)(smWl + sidx + 8) = rg[7];
        __syncthreads();
        if (c + 1 < nchunk) loadregs(c + 1);

#pragma unroll
        for (int ks = 0; ks < 4; ks++) {
            const uint32_t kb = (uint32_t)ks << 5;
            uint32_t ahf[2][4], alf[2][4];
            ldsm4(ahf[0], aA + kb);
            ldsm4(ahf[1], aA + TOFF + kb);
            ldsm4(alf[0], aA + PLANE + kb);
            ldsm4(alf[1], aA + PLANE + TOFF + kb);
            uint32_t bhf[4][2], blf[4][2], tmp[4];
            ldsm4(tmp, aW + kb);
            bhf[0][0] = tmp[0]; bhf[0][1] = tmp[1]; bhf[1][0] = tmp[2]; bhf[1][1] = tmp[3];
            ldsm4(tmp, aW + TOFF + kb);
            bhf[2][0] = tmp[0]; bhf[2][1] = tmp[1]; bhf[3][0] = tmp[2]; bhf[3][1] = tmp[3];
            ldsm4(tmp, aW + PLANE + kb);
            blf[0][0] = tmp[0]; blf[0][1] = tmp[1]; blf[1][0] = tmp[2]; blf[1][1] = tmp[3];
            ldsm4(tmp, aW + PLANE + TOFF + kb);
            blf[2][0] = tmp[0]; blf[2][1] = tmp[1]; blf[3][0] = tmp[2]; blf[3][1] = tmp[3];
#pragma unroll
            for (int u = 0; u < 4; u++) {
#pragma unroll
                for (int t = 0; t < 2; t++) {
                    MMA_BF16(acc[t][u], ahf[t][0], ahf[t][1], ahf[t][2], ahf[t][3],
                             bhf[u][0], bhf[u][1]);
                    MMA_BF16(acc[t][u], ahf[t][0], ahf[t][1], ahf[t][2], ahf[t][3],
                             blf[u][0], blf[u][1]);
                    MMA_BF16(acc[t][u], alf[t][0], alf[t][1], alf[t][2], alf[t][3],
                             bhf[u][0], bhf[u][1]);
                }
            }
        }
    }

#pragma unroll
    for (int t = 0; t < 2; t++) {
        const int r0 = m0 + wy * 32 + t * 16 + r8;
#pragma unroll
        for (int u = 0; u < 4; u++) {
            const int col = n0 + wx * 32 + u * 8 + q2;
            const float b0 = bias[col], b1 = bias[col + 1];
            const float v00 = acc[t][u][0] + b0, v01 = acc[t][u][1] + b1;
            const float v10 = acc[t][u][2] + b0, v11 = acc[t][u][3] + b1;
            if (OUTF32) {
                *(float2*)(Y + (size_t)r0 * N + col) = make_float2(v00, v01);
                *(float2*)(Y + (size_t)(r0 + 8) * N + col) = make_float2(v10, v11);
            } else {
                __nv_bfloat16 h0, h1, l0, l1;
                split1(v00, h0, l0); split1(v01, h1, l1);
                *(uint32_t*)(Yh + (size_t)r0 * N + col) = pack_bf16(h0, h1);
                *(uint32_t*)(Yl + (size_t)r0 * N + col) = pack_bf16(l0, l1);
                split1(v10, h0, l0); split1(v11, h1, l1);
                *(uint32_t*)(Yh + (size_t)(r0 + 8) * N + col) = pack_bf16(h0, h1);
                *(uint32_t*)(Yl + (size_t)(r0 + 8) * N + col) = pack_bf16(l0, l1);
            }
        }
    }
}

// ============================================================================
// scores v3: 256 thr, tile 128x64, 2 CTAs/SM. E = exp(S*0.125) masked causal.
// smem: Qh|Ql (128x64 @72) | Kh|Kl (64x64 @72); F-stage overlays Q region.
// grid = (272, BHT): qt via cum(qt)=qt(qt+1), kt2 = 64-col tile index.
// ============================================================================
#define KOFF (2 * PLANE)              // 36864
#define KPLANE (64 * GP * 2)          // 9216
#define SCORES_SMEM (2 * PLANE + 2 * KPLANE)   // 55296
#define FP2 68

__global__ void __launch_bounds__(256, 2) scores_mma(void)
{
    int idx = blockIdx.x;
    int qt = 0;
    while ((qt + 1) * (qt + 2) <= idx) qt++;
    const int kt2 = idx - qt * (qt + 1);
    const int bh = blockIdx.y;
    const int b = bh >> 4;
    const int h = bh & 15;
    const int q0 = qt << 7;
    const int k0g = kt2 << 6;

    extern __shared__ char sm[];
    const uint32_t sb = smem_u32(sm);
    __nv_bfloat16* Qh = (__nv_bfloat16*)(sm);
    __nv_bfloat16* Ql = (__nv_bfloat16*)(sm + PLANE);
    __nv_bfloat16* Kh = (__nv_bfloat16*)(sm + KOFF);
    __nv_bfloat16* Kl = (__nv_bfloat16*)(sm + KOFF + KPLANE);

    const int tid = threadIdx.x;
    const int lane = tid & 31;
    const int wid = tid >> 5;       // 0..7
    const int wy = wid >> 1;        // 0..3
    const int wx = wid & 1;         // 0..1

    // stage Q (128x64): thread -> (row = tid>>1, 32 cols); K (64x64): (tid>>2, 16 cols)
    {
        const int row = tid >> 1;
        const int k0 = (tid & 1) << 5;
        const size_t qoff = ((size_t)b * SS + q0 + row) * DD + h * DK + k0;
        const int sidx = row * GP + k0;
#pragma unroll
        for (int i = 0; i < 4; i++) {
            *(uint4*)(Qh + sidx + i * 8) = *(const uint4*)(g_Qh + qoff + i * 8);
            *(uint4*)(Ql + sidx + i * 8) = *(const uint4*)(g_Ql + qoff + i * 8);
        }
        const int krow = tid >> 2;
        const int kk0 = (tid & 3) << 4;
        const size_t koff = ((size_t)b * SS + k0g + krow) * DD + h * DK + kk0;
        const int kidx = krow * GP + kk0;
        *(uint4*)(Kh + kidx)     = *(const uint4*)(g_Kh + koff);
        *(uint4*)(Kh + kidx + 8) = *(const uint4*)(g_Kh + koff + 8);
        *(uint4*)(Kl + kidx)     = *(const uint4*)(g_Kl + koff);
        *(uint4*)(Kl + kidx + 8) = *(const uint4*)(g_Kl + koff + 8);
    }
    __syncthreads();

    const int lr = lane & 7;
    const int lm01 = (lane >> 3) & 1;
    const int lm23 = lane >> 4;
    const uint32_t aQ = sb + (uint32_t)((((wy * 32 + lm01 * 8 + lr) * GP) + lm23 * 8) << 1);
    const uint32_t aK = sb + KOFF +
        (uint32_t)((((wx * 32 + lm23 * 8 + lr) * GP) + lm01 * 8) << 1);

    float acc[2][4][4];
#pragma unroll
    for (int t = 0; t < 2; t++)
#pragma unroll
        for (int u = 0; u < 4; u++)
#pragma unroll
            for (int i = 0; i < 4; i++) acc[t][u][i] = 0.f;

    const int r8 = lane >> 2;
    const int q2 = (lane & 3) << 1;

#pragma unroll
    for (int ks = 0; ks < 4; ks++) {
        const uint32_t kb = (uint32_t)ks << 5;
        uint32_t ahf[2][4], alf[2][4];
        ldsm4(ahf[0], aQ + kb);
        ldsm4(ahf[1], aQ + TOFF + kb);
        ldsm4(alf[0], aQ + PLANE + kb);
        ldsm4(alf[1], aQ + PLANE + TOFF + kb);
        uint32_t bhf[4][2], blf[4][2], tmp[4];
        ldsm4(tmp, aK + kb);
        bhf[0][0] = tmp[0]; bhf[0][1] = tmp[1]; bhf[1][0] = tmp[2]; bhf[1][1] = tmp[3];
        ldsm4(tmp, aK + TOFF + kb);
        bhf[2][0] = tmp[0]; bhf[2][1] = tmp[1]; bhf[3][0] = tmp[2]; bhf[3][1] = tmp[3];
        ldsm4(tmp, aK + KPLANE + kb);
        blf[0][0] = tmp[0]; blf[0][1] = tmp[1]; blf[1][0] = tmp[2]; blf[1][1] = tmp[3];
        ldsm4(tmp, aK + KPLANE + TOFF + kb);
        blf[2][0] = tmp[0]; blf[2][1] = tmp[1]; blf[3][0] = tmp[2]; blf[3][1] = tmp[3];
#pragma unroll
        for (int u = 0; u < 4; u++) {
#pragma unroll
            for (int t = 0; t < 2; t++) {
                MMA_BF16(acc[t][u], ahf[t][0], ahf[t][1], ahf[t][2], ahf[t][3],
                         bhf[u][0], bhf[u][1]);
                MMA_BF16(acc[t][u], ahf[t][0], ahf[t][1], ahf[t][2], ahf[t][3],
                         blf[u][0], blf[u][1]);
                MMA_BF16(acc[t][u], alf[t][0], alf[t][1], alf[t][2], alf[t][3],
                         bhf[u][0], bhf[u][1]);
            }
        }
    }

    // ---- epilogue: stage fp32 acc into F (overlays Q region), then coalesced
    float* F = (float*)sm;
    __syncthreads();                          // all ldsm reads of Q done
#pragma unroll
    for (int t = 0; t < 2; t++) {
        const int rl = wy * 32 + t * 16 + r8;
#pragma unroll
        for (int u = 0; u < 4; u++) {
            const int cl = wx * 32 + u * 8 + q2;
            *(float2*)(F + rl * FP2 + cl)       = make_float2(acc[t][u][0], acc[t][u][1]);
            *(float2*)(F + (rl + 8) * FP2 + cl) = make_float2(acc[t][u][2], acc[t][u][3]);
        }
    }
    __syncthreads();

    const float scale = 0.125f;
    const int rid = tid >> 1;                 // 0..127
    const int cb = (tid & 1) << 5;            // 0 or 32
    const int grow = q0 + rid;
    float s = 0.f;
#pragma unroll
    for (int g = 0; g < 4; g++) {
        const int c0 = cb + g * 8;
        const float4 v0 = *(const float4*)(F + rid * FP2 + c0);
        const float4 v1 = *(const float4*)(F + rid * FP2 + c0 + 4);
        const float vv[8] = {v0.x, v0.y, v0.z, v0.w, v1.x, v1.y, v1.z, v1.w};
        uint32_t hp[4], lp[4];
#pragma unroll
        for (int j = 0; j < 8; j += 2) {
            const int colg = k0g + c0 + j;
            const float e0 = (colg     <= grow) ? __expf(vv[j]     * scale) : 0.f;
            const float e1 = (colg + 1 <= grow) ? __expf(vv[j + 1] * scale) : 0.f;
            s += e0 + e1;
            __nv_bfloat16 h0, h1, l0, l1;
            split1(e0, h0, l0); split1(e1, h1, l1);
            hp[j >> 1] = pack_bf16(h0, h1);
            lp[j >> 1] = pack_bf16(l0, l1);
        }
        const size_t off = ((size_t)bh * SS + grow) * SS + k0g + c0;
        *(uint4*)(g_Ph + off) = make_uint4(hp[0], hp[1], hp[2], hp[3]);
        *(uint4*)(g_Pl + off) = make_uint4(lp[0], lp[1], lp[2], lp[3]);
    }
    // row-sum across the 2 threads of this row
    s += __shfl_xor_sync(0xFFFFFFFFu, s, 1);
    if ((tid & 1) == 0)
        g_RS[((size_t)bh * SS + grow) * 32 + kt2] = s;
}

// ============================================================================
// AW[b,q,k] = sum_h E[b,h,q,k] * inv[b,h,q]; one block per (b,q)
// ============================================================================
__global__ __launch_bounds__(512) void aw_kernel(float* __restrict__ AW)
{
    const int q = blockIdx.x & (SS - 1);
    const int b = blockIdx.x >> 11;
    const int qt = q >> 7;
    const int bound = (qt + 1) << 7;
    const int nkt = 2 * qt + 2;

    __shared__ float inv[HH];
    const int tid = threadIdx.x;
    if (tid < HH) {
        const float* rp = g_RS + ((size_t)(b * HH + tid) * SS + q) * 32;
        float s = 0.f;
        for (int k = 0; k < nkt; k++) s += rp[k];
        inv[tid] = 1.0f / s;
    }
    __syncthreads();

    float* AWrow = AW + ((size_t)b * SS + q) * SS;
    for (int k = tid << 1; k < SS; k += 1024) {
        float2 o = make_float2(0.f, 0.f);
        if (k < bound) {
#pragma unroll
            for (int h = 0; h < HH; h++) {
                const size_t off = ((size_t)(b * HH + h) * SS + q) * SS + k;
                const __nv_bfloat162 vh = *(const __nv_bfloat162*)(g_Ph + off);
                const __nv_bfloat162 vl = *(const __nv_bfloat162*)(g_Pl + off);
                const float iv = inv[h];
                o.x += (__bfloat162float(vh.x) + __bfloat162float(vl.x)) * iv;
                o.y += (__bfloat162float(vh.y) + __bfloat162float(vl.y)) * iv;
            }
        }
        *(float2*)(AWrow + k) = o;
    }
}

// ============================================================================
// pv: C = (E @ V) * inv  (V = K planes), ldmatrix frags, reg-pipelined loads
// CTA: (qt128 desc, bh), 512 thr, warp tile 16x32
// ============================================================================
#define VPLANE (64 * GP * 2)                        // 9216
#define PV_SMEM (2 * PLANE + 2 * VPLANE + 512)      // + sinv[128]

__global__ void __launch_bounds__(512, 1) pv_mma(void)
{
    const int qt = 15 - blockIdx.x;                 // longest first
    const int bh = blockIdx.y;
    const int b = bh >> 4;
    const int h = bh & 15;
    const int q0 = qt << 7;

    extern __shared__ char sm[];
    const uint32_t sb = smem_u32(sm);
    __nv_bfloat16* Ph = (__nv_bfloat16*)(sm);
    __nv_bfloat16* Pl = (__nv_bfloat16*)(sm + PLANE);
    __nv_bfloat16* Vh = (__nv_bfloat16*)(sm + 2 * PLANE);
    __nv_bfloat16* Vl = (__nv_bfloat16*)(sm + 2 * PLANE + VPLANE);
    float* sinv = (float*)(sm + 2 * PLANE + 2 * VPLANE);

    const int tid = threadIdx.x;
    const int lane = tid & 31;
    const int wid = tid >> 5;
    const int wy = wid >> 1;
    const int wx = wid & 1;

    if (tid < 128) {
        const float* rp = g_RS + ((size_t)bh * SS + q0 + tid) * 32;
        float s = 0.f;
        const int nkt = 2 * qt + 2;
        for (int k = 0; k < nkt; k++) s += rp[k];
        sinv[tid] = 1.0f / s;
    }

    const int lr = lane & 7;
    const int lm01 = (lane >> 3) & 1;
    const int lm23 = lane >> 4;
    const uint32_t aP = sb + (uint32_t)((((wy * 16 + lm01 * 8 + lr) * GP) + lm23 * 8) << 1);
    const uint32_t aV = sb + 2 * PLANE +
        (uint32_t)((((lm01 * 8 + lr) * GP) + wx * 32 + lm23 * 8) << 1);

    const int r8 = lane >> 2;
    const int q2 = (lane & 3) << 1;

    float acc[4][4];
#pragma unroll
    for (int u = 0; u < 4; u++)
#pragma unroll
        for (int i = 0; i < 4; i++) acc[u][i] = 0.f;

    const int prow_s = tid >> 2;
    const int pk0 = (tid & 3) << 4;
    const int krow = tid >> 3;
    const int vd0 = (tid & 7) << 3;

    const int nchunk = 2 * qt + 2;
    uint4 rp[4], rv[2];
    auto loadregs = [&](int kt) {
        const int kc = kt << 6;
        const size_t poff = ((size_t)bh * SS + q0 + prow_s) * SS + kc + pk0;
        rp[0] = *(const uint4*)(g_Ph + poff);
        rp[1] = *(const uint4*)(g_Ph + poff + 8);
        rp[2] = *(const uint4*)(g_Pl + poff);
        rp[3] = *(const uint4*)(g_Pl + poff + 8);
        const size_t voff = ((size_t)b * SS + kc + krow) * DD + h * DK + vd0;
        rv[0] = *(const uint4*)(g_Kh + voff);
        rv[1] = *(const uint4*)(g_Kl + voff);
    };

    loadregs(0);
    for (int kt = 0; kt < nchunk; kt++) {
        if (kt > 0) __syncthreads();
        {
            const int sidx = prow_s * GP + pk0;
            *(uint4*)(Ph + sidx)     = rp[0];
            *(uint4*)(Ph + sidx + 8) = rp[1];
            *(uint4*)(Pl + sidx)     = rp[2];
            *(uint4*)(Pl + sidx + 8) = rp[3];
            const int vidx = krow * GP + vd0;
            *(uint4*)(Vh + vidx) = rv[0];
            *(uint4*)(Vl + vidx) = rv[1];
        }
        __syncthreads();
        if (kt + 1 < nchunk) loadregs(kt + 1);

#pragma unroll
        for (int ks = 0; ks < 4; ks++) {
            const uint32_t kb = (uint32_t)ks << 5;
            const uint32_t vkb = (uint32_t)ks * TOFF;
            uint32_t ahf[4], alf[4];
            ldsm4(ahf, aP + kb);
            ldsm4(alf, aP + PLANE + kb);
            uint32_t bhf[4][2], blf[4][2], tmp[4];
            ldsm4t(tmp, aV + vkb);
            bhf[0][0] = tmp[0]; bhf[0][1] = tmp[1]; bhf[1][0] = tmp[2]; bhf[1][1] = tmp[3];
            ldsm4t(tmp, aV + vkb + 32);
            bhf[2][0] = tmp[0]; bhf[2][1] = tmp[1]; bhf[3][0] = tmp[2]; bhf[3][1] = tmp[3];
            ldsm4t(tmp, aV + VPLANE + vkb);
            blf[0][0] = tmp[0]; blf[0][1] = tmp[1]; blf[1][0] = tmp[2]; blf[1][1] = tmp[3];
            ldsm4t(tmp, aV + VPLANE + vkb + 32);
            blf[2][0] = tmp[0]; blf[2][1] = tmp[1]; blf[3][0] = tmp[2]; blf[3][1] = tmp[3];
#pragma unroll
            for (int u = 0; u < 4; u++) {
                MMA_BF16(acc[u], ahf[0], ahf[1], ahf[2], ahf[3], bhf[u][0], bhf[u][1]);
                MMA_BF16(acc[u], ahf[0], ahf[1], ahf[2], ahf[3], blf[u][0], blf[u][1]);
                MMA_BF16(acc[u], alf[0], alf[1], alf[2], alf[3], bhf[u][0], bhf[u][1]);
            }
        }
    }

    // epilogue -> C bf16 hi/lo planes (normalized)
    const int rl0 = wy * 16 + r8;
    const float iv0 = sinv[rl0];
    const float iv1 = sinv[rl0 + 8];
    const int r0 = q0 + rl0;
#pragma unroll
    for (int u = 0; u < 4; u++) {
        const int d = wx * 32 + u * 8 + q2;
        const size_t o0 = ((size_t)b * SS + r0) * DD + h * DK + d;
        const size_t o1 = ((size_t)b * SS + r0 + 8) * DD + h * DK + d;
        __nv_bfloat16 h0, h1, l0, l1;
        split1(acc[u][0] * iv0, h0, l0); split1(acc[u][1] * iv0, h1, l1);
        *(uint32_t*)(g_Ch + o0) = pack_bf16(h0, h1);
        *(uint32_t*)(g_Cl + o0) = pack_bf16(l0, l1);
        split1(acc[u][2] * iv1, h0, l0); split1(acc[u][3] * iv1, h1, l1);
        *(uint32_t*)(g_Ch + o1) = pack_bf16(h0, h1);
        *(uint32_t*)(g_Cl + o1) = pack_bf16(l0, l1);
    }
}

// ============================================================================
// launch — multi-stream graph: cvt -> {gemmQ || gemmK} -> scores
//          -> {aw || (pv -> gemmO)} -> join
// ============================================================================
extern "C" void kernel_launch(void* const* d_in, const int* in_sizes, int n_in,
                              void* d_out, int out_size)
{
    const float* x    = (const float*)d_in[0];
    const float* z    = (const float*)d_in[1];
    // d_in[2] = mask (causal tril; handled analytically)
    const float* wq_w = (const float*)d_in[3];
    const float* wq_b = (const float*)d_in[4];
    const float* wk_w = (const float*)d_in[5];
    const float* wk_b = (const float*)d_in[6];
    // d_in[7], d_in[8] = wv (dead param in reference: v uses wk)
    const float* wo_w = (const float*)d_in[9];
    const float* wo_b = (const float*)d_in[10];

    float* out = (float*)d_out;                              // [B,S,D]
    float* AW  = out + (size_t)BB * SS * DD;                 // [B,S,S]

    __nv_bfloat16 *pXh, *pXl, *pZh, *pZl, *pQh, *pQl, *pKh, *pKl, *pCh, *pCl;
    __nv_bfloat16 *pWqh, *pWql, *pWkh, *pWkl, *pWoh, *pWol;
    cudaGetSymbolAddress((void**)&pXh, g_Xh); cudaGetSymbolAddress((void**)&pXl, g_Xl);
    cudaGetSymbolAddress((void**)&pZh, g_Zh); cudaGetSymbolAddress((void**)&pZl, g_Zl);
    cudaGetSymbolAddress((void**)&pQh, g_Qh); cudaGetSymbolAddress((void**)&pQl, g_Ql);
    cudaGetSymbolAddress((void**)&pKh, g_Kh); cudaGetSymbolAddress((void**)&pKl, g_Kl);
    cudaGetSymbolAddress((void**)&pCh, g_Ch); cudaGetSymbolAddress((void**)&pCl, g_Cl);
    cudaGetSymbolAddress((void**)&pWqh, g_Wqh); cudaGetSymbolAddress((void**)&pWql, g_Wql);
    cudaGetSymbolAddress((void**)&pWkh, g_Wkh); cudaGetSymbolAddress((void**)&pWkl, g_Wkl);
    cudaGetSymbolAddress((void**)&pWoh, g_Woh); cudaGetSymbolAddress((void**)&pWol, g_Wol);

    static cudaStream_t s1 = nullptr;
    static cudaEvent_t e0 = nullptr, e1 = nullptr, e2 = nullptr, e3 = nullptr;
    static int smem_set = 0;
    if (!smem_set) {
        cudaFuncSetAttribute(gemm_pre<true>,  cudaFuncAttributeMaxDynamicSharedMemorySize, GEMM_SMEM);
        cudaFuncSetAttribute(gemm_pre<false>, cudaFuncAttributeMaxDynamicSharedMemorySize, GEMM_SMEM);
        cudaFuncSetAttribute(scores_mma, cudaFuncAttributeMaxDynamicSharedMemorySize, SCORES_SMEM);
        cudaFuncSetAttribute(pv_mma, cudaFuncAttributeMaxDynamicSharedMemorySize, PV_SMEM);
        cudaStreamCreateWithFlags(&s1, cudaStreamNonBlocking);
        cudaEventCreateWithFlags(&e0, cudaEventDisableTiming);
        cudaEventCreateWithFlags(&e1, cudaEventDisableTiming);
        cudaEventCreateWithFlags(&e2, cudaEventDisableTiming);
        cudaEventCreateWithFlags(&e3, cudaEventDisableTiming);
        smem_set = 1;
    }

    // split inputs + weights (one fused launch)
    cvt_split_all<<<11264, 256>>>(x, z, wq_w, wk_w, wo_w);

    // fork: gemmQ on default, gemmK on s1
    cudaEventRecord(e0, 0);
    cudaStreamWaitEvent(s1, e0, 0);

    const dim3 gProj(DD / 128, MROWS / 128);                 // (8,32)
    gemm_pre<false><<<gProj, 512, GEMM_SMEM>>>(pXh, pXl, pWqh, pWql, wq_b,
                                               nullptr, pQh, pQl, DD, DD);
    gemm_pre<false><<<gProj, 512, GEMM_SMEM, s1>>>(pZh, pZl, pWkh, pWkl, wk_b,
                                                   nullptr, pKh, pKl, DD, DD);
    cudaEventRecord(e1, s1);
    cudaStreamWaitEvent(0, e1, 0);

    scores_mma<<<dim3(272, BHT), 256, SCORES_SMEM>>>();      // causal 128x64 tiles

    // fork: aw on s1, pv+gemmO on default
    cudaEventRecord(e2, 0);
    cudaStreamWaitEvent(s1, e2, 0);

    aw_kernel<<<BB * SS, 512, 0, s1>>>(AW);

    pv_mma<<<dim3(16, BHT), 512, PV_SMEM>>>();

    gemm_pre<true><<<gProj, 512, GEMM_SMEM>>>(pCh, pCl, pWoh, pWol, wo_b,
                                              out, nullptr, nullptr, DD, DD);

    // join aw back to default stream
    cudaEventRecord(e3, s1);
    cudaStreamWaitEvent(0, e3, 0);
}

// round 16
// speedup vs baseline: 1.0813x; 1.0813x over previous
#include <cuda_runtime.h>
#include <cuda_bf16.h>
#include <cstdint>
#include <math.h>

// Problem dims
#define BB 2
#define SS 2048
#define DD 1024
#define HH 16
#define DK 64
#define MROWS (BB * SS)   // 4096
#define BHT (BB * HH)     // 32

// -------- scratch (static __device__ globals; no allocation allowed) --------
__device__ __nv_bfloat16 g_Ph[(size_t)BB * HH * SS * SS];         // 256 MB E hi (exp scores)
__device__ __nv_bfloat16 g_Pl[(size_t)BB * HH * SS * SS];         // 256 MB E lo
__device__ float g_INV[(size_t)BHT * SS];                         // 256 KB per-row inv rowsum

// bf16 hi/lo planes
__device__ __nv_bfloat16 g_Xh[(size_t)MROWS * DD], g_Xl[(size_t)MROWS * DD];
__device__ __nv_bfloat16 g_Zh[(size_t)MROWS * DD], g_Zl[(size_t)MROWS * DD];
__device__ __nv_bfloat16 g_Qh[(size_t)MROWS * DD], g_Ql[(size_t)MROWS * DD];
__device__ __nv_bfloat16 g_Kh[(size_t)MROWS * DD], g_Kl[(size_t)MROWS * DD];
__device__ __nv_bfloat16 g_Ch[(size_t)MROWS * DD], g_Cl[(size_t)MROWS * DD];
__device__ __nv_bfloat16 g_Wqh[(size_t)DD * DD], g_Wql[(size_t)DD * DD];
__device__ __nv_bfloat16 g_Wkh[(size_t)DD * DD], g_Wkl[(size_t)DD * DD];
__device__ __nv_bfloat16 g_Woh[(size_t)DD * DD], g_Wol[(size_t)DD * DD];

// ============================================================================
// helpers
// ============================================================================
__device__ __forceinline__ uint32_t smem_u32(const void* p) {
    uint32_t a;
    asm("{ .reg .u64 t; cvta.to.shared.u64 t, %1; cvt.u32.u64 %0, t; }" : "=r"(a) : "l"(p));
    return a;
}

__device__ __forceinline__ uint32_t pack_bf16(__nv_bfloat16 a, __nv_bfloat16 b) {
    return (uint32_t)__bfloat16_as_ushort(a) | ((uint32_t)__bfloat16_as_ushort(b) << 16);
}

// cheap split: hi = truncated top-16 bits (free), lo = rn(v - hi)
__device__ __forceinline__ void split1(float v, __nv_bfloat16& h, __nv_bfloat16& l) {
    const uint32_t u = __float_as_uint(v);
    h = __ushort_as_bfloat16((unsigned short)(u >> 16));
    const float hf = __uint_as_float(u & 0xFFFF0000u);
    l = __float2bfloat16_rn(v - hf);
}

#define MMA_BF16(C, A0, A1, A2, A3, B0, B1) \
    asm volatile( \
        "mma.sync.aligned.m16n8k16.row.col.f32.bf16.bf16.f32 " \
        "{%0,%1,%2,%3}, {%4,%5,%6,%7}, {%8,%9}, {%0,%1,%2,%3};" \
        : "+f"((C)[0]), "+f"((C)[1]), "+f"((C)[2]), "+f"((C)[3]) \
        : "r"(A0), "r"(A1), "r"(A2), "r"(A3), "r"(B0), "r"(B1))

__device__ __forceinline__ void ldsm4(uint32_t* r, uint32_t addr) {
    asm volatile("ldmatrix.sync.aligned.m8n8.x4.shared.b16 {%0,%1,%2,%3}, [%4];"
        : "=r"(r[0]), "=r"(r[1]), "=r"(r[2]), "=r"(r[3]) : "r"(addr));
}
__device__ __forceinline__ void ldsm4t(uint32_t* r, uint32_t addr) {
    asm volatile("ldmatrix.sync.aligned.m8n8.x4.trans.shared.b16 {%0,%1,%2,%3}, [%4];"
        : "=r"(r[0]), "=r"(r[1]), "=r"(r[2]), "=r"(r[3]) : "r"(addr));
}

// shared-memory pitch (bf16 elements): 72 -> 144B rows -> conflict-free LDSM
#define GP 72
#define PLANE (128 * GP * 2)          // 18432 bytes per 128-row plane
#define TOFF  (16 * GP * 2)           // byte offset of 16 rows = 2304

// ============================================================================
// fused fp32 -> bf16 hi/lo split over {x, z, wq, wk, wo}
// ============================================================================
#define NX ((size_t)MROWS * DD)       // 4194304
#define NW ((size_t)DD * DD)          // 1048576

__global__ __launch_bounds__(256) void cvt_split_all(
    const float* __restrict__ x, const float* __restrict__ z,
    const float* __restrict__ wq, const float* __restrict__ wk,
    const float* __restrict__ wo)
{
    const size_t i4 = ((size_t)blockIdx.x * 256 + threadIdx.x) * 4;
    const float* src;
    __nv_bfloat16 *hi, *lo;
    if (i4 < NX)               { src = x  + i4;                 hi = g_Xh + i4;                 lo = g_Xl + i4; }
    else if (i4 < 2 * NX)      { size_t j = i4 - NX;            src = z  + j; hi = g_Zh + j;    lo = g_Zl + j; }
    else if (i4 < 2 * NX + NW) { size_t j = i4 - 2 * NX;        src = wq + j; hi = g_Wqh + j;   lo = g_Wql + j; }
    else if (i4 < 2 * NX + 2 * NW) { size_t j = i4 - 2 * NX - NW; src = wk + j; hi = g_Wkh + j; lo = g_Wkl + j; }
    else                       { size_t j = i4 - 2 * NX - 2 * NW; src = wo + j; hi = g_Woh + j; lo = g_Wol + j; }

    const float4 v = *(const float4*)src;
    __nv_bfloat16 h0, h1, h2, h3, l0, l1, l2, l3;
    split1(v.x, h0, l0); split1(v.y, h1, l1);
    split1(v.z, h2, l2); split1(v.w, h3, l3);
    uint2 ph, pl;
    ph.x = pack_bf16(h0, h1); ph.y = pack_bf16(h2, h3);
    pl.x = pack_bf16(l0, l1); pl.y = pack_bf16(l2, l3);
    *(uint2*)hi = ph;
    *(uint2*)lo = pl;
}

// ============================================================================
// bf16x3 GEMM (ldmatrix frags, reg-pipelined loads): Y = A @ W^T + bias
// 512 thr / 16 warps, CTA 128x128, warp 32x32, K-chunk 64
// ============================================================================
#define GEMM_SMEM (4 * PLANE)         // 73728

template<bool OUTF32>
__global__ void __launch_bounds__(512, 1) gemm_pre(
    const __nv_bfloat16* __restrict__ Ah_g, const __nv_bfloat16* __restrict__ Al_g,
    const __nv_bfloat16* __restrict__ Wh_g, const __nv_bfloat16* __restrict__ Wl_g,
    const float* __restrict__ bias,
    float* __restrict__ Y,
    __nv_bfloat16* __restrict__ Yh, __nv_bfloat16* __restrict__ Yl,
    int K, int N)
{
    extern __shared__ char sm[];
    const uint32_t sb = smem_u32(sm);
    __nv_bfloat16* smAh = (__nv_bfloat16*)(sm);
    __nv_bfloat16* smAl = (__nv_bfloat16*)(sm + PLANE);
    __nv_bfloat16* smWh = (__nv_bfloat16*)(sm + 2 * PLANE);
    __nv_bfloat16* smWl = (__nv_bfloat16*)(sm + 3 * PLANE);

    const int tid = threadIdx.x;
    const int lane = tid & 31;
    const int wid = tid >> 5;
    const int wy = wid >> 2;
    const int wx = wid & 3;
    const int m0 = blockIdx.y * 128;
    const int n0 = blockIdx.x * 128;

    const int srow = tid >> 2;
    const int sk0 = (tid & 3) << 4;
    const __nv_bfloat16* pAh = Ah_g + (size_t)(m0 + srow) * K + sk0;
    const __nv_bfloat16* pAl = Al_g + (size_t)(m0 + srow) * K + sk0;
    const __nv_bfloat16* pWh = Wh_g + (size_t)(n0 + srow) * K + sk0;
    const __nv_bfloat16* pWl = Wl_g + (size_t)(n0 + srow) * K + sk0;
    const int sidx = srow * GP + sk0;

    const int lr = lane & 7;
    const int lm01 = (lane >> 3) & 1;
    const int lm23 = lane >> 4;
    const uint32_t aA = sb + (uint32_t)((((wy * 32 + lm01 * 8 + lr) * GP) + lm23 * 8) << 1);
    const uint32_t aW = sb + 2 * PLANE +
        (uint32_t)((((wx * 32 + lm23 * 8 + lr) * GP) + lm01 * 8) << 1);

    float acc[2][4][4];
#pragma unroll
    for (int t = 0; t < 2; t++)
#pragma unroll
        for (int u = 0; u < 4; u++)
#pragma unroll
            for (int i = 0; i < 4; i++) acc[t][u][i] = 0.f;

    const int r8 = lane >> 2;
    const int q2 = (lane & 3) << 1;
    const int nchunk = K >> 6;

    uint4 rg[8];
    auto loadregs = [&](int c) {
        const int kc = c << 6;
        rg[0] = *(const uint4*)(pAh + kc); rg[1] = *(const uint4*)(pAh + kc + 8);
        rg[2] = *(const uint4*)(pAl + kc); rg[3] = *(const uint4*)(pAl + kc + 8);
        rg[4] = *(const uint4*)(pWh + kc); rg[5] = *(const uint4*)(pWh + kc + 8);
        rg[6] = *(const uint4*)(pWl + kc); rg[7] = *(const uint4*)(pWl + kc + 8);
    };

    loadregs(0);
    for (int c = 0; c < nchunk; c++) {
        if (c > 0) __syncthreads();
        *(uint4*)(smAh + sidx)     = rg[0]; *(uint4*)(smAh + sidx + 8) = rg[1];
        *(uint4*)(smAl + sidx)     = rg[2]; *(uint4*)(smAl + sidx + 8) = rg[3];
        *(uint4*)(smWh + sidx)     = rg[4]; *(uint4*)(smWh + sidx + 8) = rg[5];
        *(uint4*)(smWl + sidx)     = rg[6]; *(uint4*)(smWl + sidx + 8) = rg[7];
        __syncthreads();
        if (c + 1 < nchunk) loadregs(c + 1);

#pragma unroll
        for (int ks = 0; ks < 4; ks++) {
            const uint32_t kb = (uint32_t)ks << 5;
            uint32_t ahf[2][4], alf[2][4];
            ldsm4(ahf[0], aA + kb);
            ldsm4(ahf[1], aA + TOFF + kb);
            ldsm4(alf[0], aA + PLANE + kb);
            ldsm4(alf[1], aA + PLANE + TOFF + kb);
            uint32_t bhf[4][2], blf[4][2], tmp[4];
            ldsm4(tmp, aW + kb);
            bhf[0][0] = tmp[0]; bhf[0][1] = tmp[1]; bhf[1][0] = tmp[2]; bhf[1][1] = tmp[3];
            ldsm4(tmp, aW + TOFF + kb);
            bhf[2][0] = tmp[0]; bhf[2][1] = tmp[1]; bhf[3][0] = tmp[2]; bhf[3][1] = tmp[3];
            ldsm4(tmp, aW + PLANE + kb);
            blf[0][0] = tmp[0]; blf[0][1] = tmp[1]; blf[1][0] = tmp[2]; blf[1][1] = tmp[3];
            ldsm4(tmp, aW + PLANE + TOFF + kb);
            blf[2][0] = tmp[0]; blf[2][1] = tmp[1]; blf[3][0] = tmp[2]; blf[3][1] = tmp[3];
#pragma unroll
            for (int u = 0; u < 4; u++) {
#pragma unroll
                for (int t = 0; t < 2; t++) {
                    MMA_BF16(acc[t][u], ahf[t][0], ahf[t][1], ahf[t][2], ahf[t][3],
                             bhf[u][0], bhf[u][1]);
                    MMA_BF16(acc[t][u], ahf[t][0], ahf[t][1], ahf[t][2], ahf[t][3],
                             blf[u][0], blf[u][1]);
                    MMA_BF16(acc[t][u], alf[t][0], alf[t][1], alf[t][2], alf[t][3],
                             bhf[u][0], bhf[u][1]);
                }
            }
        }
    }

#pragma unroll
    for (int t = 0; t < 2; t++) {
        const int r0 = m0 + wy * 32 + t * 16 + r8;
#pragma unroll
        for (int u = 0; u < 4; u++) {
            const int col = n0 + wx * 32 + u * 8 + q2;
            const float b0 = bias[col], b1 = bias[col + 1];
            const float v00 = acc[t][u][0] + b0, v01 = acc[t][u][1] + b1;
            const float v10 = acc[t][u][2] + b0, v11 = acc[t][u][3] + b1;
            if (OUTF32) {
                *(float2*)(Y + (size_t)r0 * N + col) = make_float2(v00, v01);
                *(float2*)(Y + (size_t)(r0 + 8) * N + col) = make_float2(v10, v11);
            } else {
                __nv_bfloat16 h0, h1, l0, l1;
                split1(v00, h0, l0); split1(v01, h1, l1);
                *(uint32_t*)(Yh + (size_t)r0 * N + col) = pack_bf16(h0, h1);
                *(uint32_t*)(Yl + (size_t)r0 * N + col) = pack_bf16(l0, l1);
                split1(v10, h0, l0); split1(v11, h1, l1);
                *(uint32_t*)(Yh + (size_t)(r0 + 8) * N + col) = pack_bf16(h0, h1);
                *(uint32_t*)(Yl + (size_t)(r0 + 8) * N + col) = pack_bf16(l0, l1);
            }
        }
    }
}

// ============================================================================
// fused attention: per (qt, bh) CTA, loop kt2 over 64-col K tiles.
//   S = Q.K^T * 0.125 ; E = exp(S) masked ; E -> smem + gmem planes ;
//   O += E @ V (V = same K smem tile via ldsm4t) ; inv computed in-kernel.
// 512 thr / 16 warps; MMA1 warp tile 32x16 (wy rows, wx n-cols);
// MMA2 warp tile 32x16 (wy rows, wx d-cols).
// smem: Qh|Ql (128x64@72, 36864) | Kh|Kl (64x64@72, 18432)
//       | Eh|El (128x64@72, 36864) | red[128][4] | sinv[128]
// ============================================================================
#define QPLANE PLANE                  // 18432 (128 rows x 64 cols @72)
#define KBASE (2 * QPLANE)            // 36864
#define KPLANE (64 * GP * 2)          // 9216
#define EBASE (KBASE + 2 * KPLANE)    // 55296
#define EPLANE PLANE                  // 18432
#define RBASE (EBASE + 2 * EPLANE)    // 92160
#define FUSED_SMEM (RBASE + 2048 + 512)   // 94720

__global__ void __launch_bounds__(512, 1) fused_attn(void)
{
    const int qt = 15 - blockIdx.x;                 // longest first
    const int bh = blockIdx.y;
    const int b = bh >> 4;
    const int h = bh & 15;
    const int q0 = qt << 7;

    extern __shared__ char sm[];
    const uint32_t sb = smem_u32(sm);
    __nv_bfloat16* Qh = (__nv_bfloat16*)(sm);
    __nv_bfloat16* Ql = (__nv_bfloat16*)(sm + QPLANE);
    __nv_bfloat16* Kh = (__nv_bfloat16*)(sm + KBASE);
    __nv_bfloat16* Kl = (__nv_bfloat16*)(sm + KBASE + KPLANE);
    __nv_bfloat16* Eh = (__nv_bfloat16*)(sm + EBASE);
    __nv_bfloat16* El = (__nv_bfloat16*)(sm + EBASE + EPLANE);
    float* red  = (float*)(sm + RBASE);             // [128][4]
    float* sinv = (float*)(sm + RBASE + 2048);      // [128]

    const int tid = threadIdx.x;
    const int lane = tid & 31;
    const int wid = tid >> 5;
    const int wy = wid >> 2;        // 0..3 : 32 rows each
    const int wx = wid & 3;         // 0..3 : 16 cols each

    // stage Q once (128x64 x2 planes)
    {
        const int row = tid >> 2;
        const int k0 = (tid & 3) << 4;
        const size_t qoff = ((size_t)b * SS + q0 + row) * DD + h * DK + k0;
        const int sidx = row * GP + k0;
        *(uint4*)(Qh + sidx)     = *(const uint4*)(g_Qh + qoff);
        *(uint4*)(Qh + sidx + 8) = *(const uint4*)(g_Qh + qoff + 8);
        *(uint4*)(Ql + sidx)     = *(const uint4*)(g_Ql + qoff);
        *(uint4*)(Ql + sidx + 8) = *(const uint4*)(g_Ql + qoff + 8);
    }

    const int lr = lane & 7;
    const int lm01 = (lane >> 3) & 1;
    const int lm23 = lane >> 4;
    const uint32_t aQ = sb + (uint32_t)((((wy * 32 + lm01 * 8 + lr) * GP) + lm23 * 8) << 1);
    const uint32_t aK = sb + KBASE +
        (uint32_t)((((wx * 16 + lm23 * 8 + lr) * GP) + lm01 * 8) << 1);
    const uint32_t aE = sb + EBASE +
        (uint32_t)((((wy * 32 + lm01 * 8 + lr) * GP) + lm23 * 8) << 1);
    const uint32_t aV = sb + KBASE +
        (uint32_t)((((lm01 * 8 + lr) * GP) + wx * 16 + lm23 * 8) << 1);

    const int r8 = lane >> 2;
    const int q2 = (lane & 3) << 1;

    float accO[2][2][4];
#pragma unroll
    for (int t = 0; t < 2; t++)
#pragma unroll
        for (int u = 0; u < 2; u++)
#pragma unroll
            for (int i = 0; i < 4; i++) accO[t][u][i] = 0.f;
    float psum[4] = {0.f, 0.f, 0.f, 0.f};

    // K staging map: thread -> (krow = tid>>3, 8 d) per plane
    const int krow = tid >> 3;
    const int kd0 = (tid & 7) << 3;
    // E copy map: row = tid>>2, 16 cols
    const int erow = tid >> 2;
    const int ec0 = (tid & 3) << 4;

    const int nkt = 2 * qt + 2;
    uint4 rv[2];
    auto loadK = [&](int kt2) {
        const size_t koff = ((size_t)b * SS + (kt2 << 6) + krow) * DD + h * DK + kd0;
        rv[0] = *(const uint4*)(g_Kh + koff);
        rv[1] = *(const uint4*)(g_Kl + koff);
    };

    loadK(0);
    for (int kt2 = 0; kt2 < nkt; kt2++) {
        // stage K (prev iter's MMA1/MMA2 reads + E copy done via last sync or Q-stage)
        if (kt2 == 0) __syncthreads();              // Q staged
        {
            const int kidx = krow * GP + kd0;
            *(uint4*)(Kh + kidx) = rv[0];
            *(uint4*)(Kl + kidx) = rv[1];
        }
        __syncthreads();
        if (kt2 + 1 < nkt) loadK(kt2 + 1);

        // ---- MMA1: S = Q . K^T  (warp 32 rows x 16 n-cols)
        float accS[2][2][4];
#pragma unroll
        for (int t = 0; t < 2; t++)
#pragma unroll
            for (int u = 0; u < 2; u++)
#pragma unroll
                for (int i = 0; i < 4; i++) accS[t][u][i] = 0.f;

#pragma unroll
        for (int ks = 0; ks < 4; ks++) {
            const uint32_t kb = (uint32_t)ks << 5;
            uint32_t ahf[2][4], alf[2][4];
            ldsm4(ahf[0], aQ + kb);
            ldsm4(ahf[1], aQ + TOFF + kb);
            ldsm4(alf[0], aQ + QPLANE + kb);
            ldsm4(alf[1], aQ + QPLANE + TOFF + kb);
            uint32_t bh2[2][2], bl2[2][2], tmp[4];
            ldsm4(tmp, aK + kb);
            bh2[0][0] = tmp[0]; bh2[0][1] = tmp[1]; bh2[1][0] = tmp[2]; bh2[1][1] = tmp[3];
            ldsm4(tmp, aK + KPLANE + kb);
            bl2[0][0] = tmp[0]; bl2[0][1] = tmp[1]; bl2[1][0] = tmp[2]; bl2[1][1] = tmp[3];
#pragma unroll
            for (int u = 0; u < 2; u++)
#pragma unroll
                for (int t = 0; t < 2; t++) {
                    MMA_BF16(accS[t][u], ahf[t][0], ahf[t][1], ahf[t][2], ahf[t][3],
                             bh2[u][0], bh2[u][1]);
                    MMA_BF16(accS[t][u], ahf[t][0], ahf[t][1], ahf[t][2], ahf[t][3],
                             bl2[u][0], bl2[u][1]);
                    MMA_BF16(accS[t][u], alf[t][0], alf[t][1], alf[t][2], alf[t][3],
                             bh2[u][0], bh2[u][1]);
                }
        }

        // ---- exp + mask + rowsum + E -> smem
        const int k0g = kt2 << 6;
        const float scale = 0.125f;
#pragma unroll
        for (int t = 0; t < 2; t++) {
#pragma unroll
            for (int u = 0; u < 2; u++) {
                const int colg = k0g + wx * 16 + u * 8 + q2;
                const int row0 = q0 + wy * 32 + t * 16 + r8;
                const float e00 = (colg     <= row0)     ? __expf(accS[t][u][0] * scale) : 0.f;
                const float e01 = (colg + 1 <= row0)     ? __expf(accS[t][u][1] * scale) : 0.f;
                const float e10 = (colg     <= row0 + 8) ? __expf(accS[t][u][2] * scale) : 0.f;
                const float e11 = (colg + 1 <= row0 + 8) ? __expf(accS[t][u][3] * scale) : 0.f;
                psum[t * 2 + 0] += e00 + e01;
                psum[t * 2 + 1] += e10 + e11;
                const int rl = wy * 32 + t * 16 + r8;
                const int cl = wx * 16 + u * 8 + q2;
                __nv_bfloat16 h0, h1, l0, l1;
                split1(e00, h0, l0); split1(e01, h1, l1);
                *(uint32_t*)(Eh + rl * GP + cl) = pack_bf16(h0, h1);
                *(uint32_t*)(El + rl * GP + cl) = pack_bf16(l0, l1);
                split1(e10, h0, l0); split1(e11, h1, l1);
                *(uint32_t*)(Eh + (rl + 8) * GP + cl) = pack_bf16(h0, h1);
                *(uint32_t*)(El + (rl + 8) * GP + cl) = pack_bf16(l0, l1);
            }
        }
        __syncthreads();   // E visible; K reads of MMA1 done

        // ---- MMA2: O += E @ V  (V = K smem via trans; warp 32 rows x 16 d)
#pragma unroll
        for (int ks = 0; ks < 4; ks++) {
            const uint32_t kb = (uint32_t)ks << 5;
            const uint32_t vkb = (uint32_t)ks * TOFF;
            uint32_t ehf[2][4], elf[2][4];
            ldsm4(ehf[0], aE + kb);
            ldsm4(ehf[1], aE + TOFF + kb);
            ldsm4(elf[0], aE + EPLANE + kb);
            ldsm4(elf[1], aE + EPLANE + TOFF + kb);
            uint32_t vh2[2][2], vl2[2][2], tmp[4];
            ldsm4t(tmp, aV + vkb);
            vh2[0][0] = tmp[0]; vh2[0][1] = tmp[1]; vh2[1][0] = tmp[2]; vh2[1][1] = tmp[3];
            ldsm4t(tmp, aV + KPLANE + vkb);
            vl2[0][0] = tmp[0]; vl2[0][1] = tmp[1]; vl2[1][0] = tmp[2]; vl2[1][1] = tmp[3];
#pragma unroll
            for (int u = 0; u < 2; u++)
#pragma unroll
                for (int t = 0; t < 2; t++) {
                    MMA_BF16(accO[t][u], ehf[t][0], ehf[t][1], ehf[t][2], ehf[t][3],
                             vh2[u][0], vh2[u][1]);
                    MMA_BF16(accO[t][u], ehf[t][0], ehf[t][1], ehf[t][2], ehf[t][3],
                             vl2[u][0], vl2[u][1]);
                    MMA_BF16(accO[t][u], elf[t][0], elf[t][1], elf[t][2], elf[t][3],
                             vh2[u][0], vh2[u][1]);
                }
        }

        // ---- E smem -> gmem planes (coalesced)
        {
            const size_t off = ((size_t)bh * SS + q0 + erow) * SS + k0g + ec0;
            const int sidx = erow * GP + ec0;
            *(uint4*)(g_Ph + off)     = *(const uint4*)(Eh + sidx);
            *(uint4*)(g_Ph + off + 8) = *(const uint4*)(Eh + sidx + 8);
            *(uint4*)(g_Pl + off)     = *(const uint4*)(El + sidx);
            *(uint4*)(g_Pl + off + 8) = *(const uint4*)(El + sidx + 8);
        }
        __syncthreads();   // MMA2 K/E reads + E copy done before next staging
    }

    // ---- rowsum reduce -> inv
#pragma unroll
    for (int t = 0; t < 2; t++)
#pragma unroll
        for (int rh = 0; rh < 2; rh++) {
            float s = psum[t * 2 + rh];
            s += __shfl_xor_sync(0xFFFFFFFFu, s, 1);
            s += __shfl_xor_sync(0xFFFFFFFFu, s, 2);
            if ((lane & 3) == 0)
                red[(wy * 32 + t * 16 + rh * 8 + r8) * 4 + wx] = s;
        }
    __syncthreads();
    if (tid < 128) {
        const float s = red[tid * 4] + red[tid * 4 + 1] + red[tid * 4 + 2] + red[tid * 4 + 3];
        const float iv = 1.0f / s;
        sinv[tid] = iv;
        g_INV[(size_t)bh * SS + q0 + tid] = iv;
    }
    __syncthreads();

    // ---- O epilogue -> C bf16 planes (normalized)
#pragma unroll
    for (int t = 0; t < 2; t++) {
        const int rl = wy * 32 + t * 16 + r8;
        const float iv0 = sinv[rl];
        const float iv1 = sinv[rl + 8];
#pragma unroll
        for (int u = 0; u < 2; u++) {
            const int d = wx * 16 + u * 8 + q2;
            const size_t o0 = ((size_t)b * SS + q0 + rl) * DD + h * DK + d;
            const size_t o1 = ((size_t)b * SS + q0 + rl + 8) * DD + h * DK + d;
            __nv_bfloat16 h0, h1, l0, l1;
            split1(accO[t][u][0] * iv0, h0, l0); split1(accO[t][u][1] * iv0, h1, l1);
            *(uint32_t*)(g_Ch + o0) = pack_bf16(h0, h1);
            *(uint32_t*)(g_Cl + o0) = pack_bf16(l0, l1);
            split1(accO[t][u][2] * iv1, h0, l0); split1(accO[t][u][3] * iv1, h1, l1);
            *(uint32_t*)(g_Ch + o1) = pack_bf16(h0, h1);
            *(uint32_t*)(g_Cl + o1) = pack_bf16(l0, l1);
        }
    }
}

// ============================================================================
// AW[b,q,k] = sum_h E[b,h,q,k] * inv[b,h,q]; one block per (b,q)
// ============================================================================
__global__ __launch_bounds__(512) void aw_kernel(float* __restrict__ AW)
{
    const int q = blockIdx.x & (SS - 1);
    const int b = blockIdx.x >> 11;
    const int qt = q >> 7;
    const int bound = (qt + 1) << 7;

    __shared__ float inv[HH];
    const int tid = threadIdx.x;
    if (tid < HH)
        inv[tid] = g_INV[(size_t)(b * HH + tid) * SS + q];
    __syncthreads();

    float* AWrow = AW + ((size_t)b * SS + q) * SS;
    for (int k = tid << 1; k < SS; k += 1024) {
        float2 o = make_float2(0.f, 0.f);
        if (k < bound) {
#pragma unroll
            for (int h = 0; h < HH; h++) {
                const size_t off = ((size_t)(b * HH + h) * SS + q) * SS + k;
                const __nv_bfloat162 vh = *(const __nv_bfloat162*)(g_Ph + off);
                const __nv_bfloat162 vl = *(const __nv_bfloat162*)(g_Pl + off);
                const float iv = inv[h];
                o.x += (__bfloat162float(vh.x) + __bfloat162float(vl.x)) * iv;
                o.y += (__bfloat162float(vh.y) + __bfloat162float(vl.y)) * iv;
            }
        }
        *(float2*)(AWrow + k) = o;
    }
}

// ============================================================================
// launch — cvt -> {gemmQ || gemmK} -> fused_attn -> {aw || gemmO} -> join
// ============================================================================
extern "C" void kernel_launch(void* const* d_in, const int* in_sizes, int n_in,
                              void* d_out, int out_size)
{
    const float* x    = (const float*)d_in[0];
    const float* z    = (const float*)d_in[1];
    // d_in[2] = mask (causal tril; handled analytically)
    const float* wq_w = (const float*)d_in[3];
    const float* wq_b = (const float*)d_in[4];
    const float* wk_w = (const float*)d_in[5];
    const float* wk_b = (const float*)d_in[6];
    // d_in[7], d_in[8] = wv (dead param in reference: v uses wk)
    const float* wo_w = (const float*)d_in[9];
    const float* wo_b = (const float*)d_in[10];

    float* out = (float*)d_out;                              // [B,S,D]
    float* AW  = out + (size_t)BB * SS * DD;                 // [B,S,S]

    __nv_bfloat16 *pXh, *pXl, *pZh, *pZl, *pQh, *pQl, *pKh, *pKl, *pCh, *pCl;
    __nv_bfloat16 *pWqh, *pWql, *pWkh, *pWkl, *pWoh, *pWol;
    cudaGetSymbolAddress((void**)&pXh, g_Xh); cudaGetSymbolAddress((void**)&pXl, g_Xl);
    cudaGetSymbolAddress((void**)&pZh, g_Zh); cudaGetSymbolAddress((void**)&pZl, g_Zl);
    cudaGetSymbolAddress((void**)&pQh, g_Qh); cudaGetSymbolAddress((void**)&pQl, g_Ql);
    cudaGetSymbolAddress((void**)&pKh, g_Kh); cudaGetSymbolAddress((void**)&pKl, g_Kl);
    cudaGetSymbolAddress((void**)&pCh, g_Ch); cudaGetSymbolAddress((void**)&pCl, g_Cl);
    cudaGetSymbolAddress((void**)&pWqh, g_Wqh); cudaGetSymbolAddress((void**)&pWql, g_Wql);
    cudaGetSymbolAddress((void**)&pWkh, g_Wkh); cudaGetSymbolAddress((void**)&pWkl, g_Wkl);
    cudaGetSymbolAddress((void**)&pWoh, g_Woh); cudaGetSymbolAddress((void**)&pWol, g_Wol);

    static cudaStream_t s1 = nullptr;
    static cudaEvent_t e0 = nullptr, e1 = nullptr, e2 = nullptr, e3 = nullptr;
    static int smem_set = 0;
    if (!smem_set) {
        cudaFuncSetAttribute(gemm_pre<true>,  cudaFuncAttributeMaxDynamicSharedMemorySize, GEMM_SMEM);
        cudaFuncSetAttribute(gemm_pre<false>, cudaFuncAttributeMaxDynamicSharedMemorySize, GEMM_SMEM);
        cudaFuncSetAttribute(fused_attn, cudaFuncAttributeMaxDynamicSharedMemorySize, FUSED_SMEM);
        cudaStreamCreateWithFlags(&s1, cudaStreamNonBlocking);
        cudaEventCreateWithFlags(&e0, cudaEventDisableTiming);
        cudaEventCreateWithFlags(&e1, cudaEventDisableTiming);
        cudaEventCreateWithFlags(&e2, cudaEventDisableTiming);
        cudaEventCreateWithFlags(&e3, cudaEventDisableTiming);
        smem_set = 1;
    }

    // split inputs + weights (one fused launch)
    cvt_split_all<<<11264, 256>>>(x, z, wq_w, wk_w, wo_w);

    // fork: gemmQ on default, gemmK on s1
    cudaEventRecord(e0, 0);
    cudaStreamWaitEvent(s1, e0, 0);

    const dim3 gProj(DD / 128, MROWS / 128);                 // (8,32)
    gemm_pre<false><<<gProj, 512, GEMM_SMEM>>>(pXh, pXl, pWqh, pWql, wq_b,
                                               nullptr, pQh, pQl, DD, DD);
    gemm_pre<false><<<gProj, 512, GEMM_SMEM, s1>>>(pZh, pZl, pWkh, pWkl, wk_b,
                                                   nullptr, pKh, pKl, DD, DD);
    cudaEventRecord(e1, s1);
    cudaStreamWaitEvent(0, e1, 0);

    fused_attn<<<dim3(16, BHT), 512, FUSED_SMEM>>>();

    // fork: aw on s1, gemmO on default
    cudaEventRecord(e2, 0);
    cudaStreamWaitEvent(s1, e2, 0);

    aw_kernel<<<BB * SS, 512, 0, s1>>>(AW);

    gemm_pre<true><<<gProj, 512, GEMM_SMEM>>>(pCh, pCl, pWoh, pWol, wo_b,
                                              out, nullptr, nullptr, DD, DD);

    // join aw back to default stream
    cudaEventRecord(e3, s1);
    cudaStreamWaitEvent(0, e3, 0);
}